// round 2
// baseline (speedup 1.0000x reference)
#include <cuda_runtime.h>
#include <math.h>

#define NN 50000
#define EE 800000
#define GG 512
#define CDIM 64

// ---------------- scratch (device globals: allocation-free) ----------------
__device__ float g_xl[NN * 256];
__device__ float g_xr[NN * 256];
__device__ float g_att[NN * 256];   // attention output accumulator (pre-LN)
__device__ float g_hA[NN * 256];    // h after layer 0 (256 wide)
__device__ float g_hB[NN * 64];     // h after layer 1
__device__ float g_hC[NN * 64];     // h after layer 2
__device__ float g_ex[EE * 4];      // exp(logit) then alpha
__device__ float g_den[NN * 4];
__device__ float g_stats[2];        // sum, sumsq for graph-layernorm
__device__ float g_Z[GG * 64];
__device__ float g_cnt[GG];

// ---------------- zero fill ----------------
__global__ void zero_kernel(float* p, int n) {
    int t = blockIdx.x * blockDim.x + threadIdx.x;
    if (t < n) p[t] = 0.f;
}

// ---------------- fused xl/xr GEMM with bias ----------------
// C tile 64x64, BK=16, 256 threads, 4x4 microtile.
#define BM 64
#define BN 64
#define BK 16
__global__ void gemm_xlr_kernel(const float* __restrict__ A, int din, int nrows,
                                const float* __restrict__ Wl, const float* __restrict__ bl,
                                const float* __restrict__ Wr, const float* __restrict__ br,
                                float* __restrict__ XL, float* __restrict__ XR, int HC) {
    __shared__ float As[BK][BM];
    __shared__ float Bs[BK][BN];
    int bm = blockIdx.x * BM;
    int bn = blockIdx.y * BN;
    const float* W;
    const float* bias;
    float* Out;
    int col0;
    if (bn < HC) { W = Wl; bias = bl; Out = XL; col0 = bn; }
    else         { W = Wr; bias = br; Out = XR; col0 = bn - HC; }

    int tid = threadIdx.x;
    int tx = tid & 15;
    int ty = tid >> 4;
    float acc[4][4] = {};

    for (int k0 = 0; k0 < din; k0 += BK) {
#pragma unroll
        for (int i = 0; i < 4; i++) {
            int idx = tid + i * 256;
            int r = idx >> 4;
            int kk = idx & 15;
            int gr = bm + r;
            As[kk][r] = (gr < nrows) ? A[(size_t)gr * din + k0 + kk] : 0.f;
        }
#pragma unroll
        for (int i = 0; i < 4; i++) {
            int idx = tid + i * 256;
            int kk = idx >> 6;
            int c = idx & 63;
            Bs[kk][c] = W[(size_t)(k0 + kk) * HC + col0 + c];
        }
        __syncthreads();
#pragma unroll
        for (int kk = 0; kk < BK; kk++) {
            float a[4], b[4];
#pragma unroll
            for (int i = 0; i < 4; i++) a[i] = As[kk][ty * 4 + i];
#pragma unroll
            for (int j = 0; j < 4; j++) b[j] = Bs[kk][tx * 4 + j];
#pragma unroll
            for (int i = 0; i < 4; i++)
#pragma unroll
                for (int j = 0; j < 4; j++) acc[i][j] += a[i] * b[j];
        }
        __syncthreads();
    }
#pragma unroll
    for (int i = 0; i < 4; i++) {
        int r = bm + ty * 4 + i;
        if (r < nrows) {
#pragma unroll
            for (int j = 0; j < 4; j++) {
                int c = col0 + tx * 4 + j;
                Out[(size_t)r * HC + c] = acc[i][j] + bias[c];
            }
        }
    }
}

// ---------------- edge logits: one warp per (edge, head). C=64 fixed. ----------------
// ex[e,h] = exp( att[h,:] . leaky_relu(xl[src,h,:] + xr[dst,h,:]) )
// den[dst,h] += ex   (no max-subtraction: alpha is shift-invariant, values O(1))
__global__ void edge_attn_kernel(const int* __restrict__ ei,
                                 const float* __restrict__ XL, const float* __restrict__ XR,
                                 const float* __restrict__ att,
                                 float* __restrict__ ex, float* __restrict__ den,
                                 int H, int HC) {
    int w = (blockIdx.x * blockDim.x + threadIdx.x) >> 5;
    int lane = threadIdx.x & 31;
    if (w >= EE * H) return;
    int e = w / H;
    int h = w - e * H;
    int src = ei[e];
    int dst = ei[EE + e];
    const float* pl = XL + (size_t)src * HC + h * CDIM;
    const float* pr = XR + (size_t)dst * HC + h * CDIM;
    const float* pa = att + h * CDIM;
    float dot = 0.f;
#pragma unroll
    for (int c = lane; c < CDIM; c += 32) {
        float s = pl[c] + pr[c];
        s = (s > 0.f) ? s : 0.2f * s;
        dot += s * pa[c];
    }
#pragma unroll
    for (int o = 16; o > 0; o >>= 1) dot += __shfl_xor_sync(0xffffffffu, dot, o);
    if (lane == 0) {
        float v = expf(dot);
        ex[e * H + h] = v;
        atomicAdd(&den[dst * H + h], v);
    }
}

// ---------------- alpha = ex / den[dst] ----------------
__global__ void alpha_kernel(const int* __restrict__ ei, float* __restrict__ ex,
                             const float* __restrict__ den, int H) {
    int t = blockIdx.x * blockDim.x + threadIdx.x;
    if (t >= EE * H) return;
    int e = t / H;
    int h = t - e * H;
    int dst = ei[EE + e];
    ex[t] = ex[t] / den[dst * H + h];
}

// ---------------- scatter: out[dst, r] += alpha[e,h] * xl[src, r] ----------------
__global__ void scatter_kernel(const int* __restrict__ ei, const float* __restrict__ XL,
                               const float* __restrict__ alpha, float* __restrict__ out,
                               int H, int hcShift, int total) {
    int t = blockIdx.x * blockDim.x + threadIdx.x;
    if (t >= total) return;
    int e = t >> hcShift;
    int r = t & ((1 << hcShift) - 1);
    int h = r >> 6;
    int src = ei[e];
    int dst = ei[EE + e];
    float a = alpha[e * H + h];
    atomicAdd(&out[((size_t)dst << hcShift) + r], a * XL[((size_t)src << hcShift) + r]);
}

// ---------------- graph-layernorm stats: global sum / sumsq of (out + bias) ----------------
__global__ void ln_stats_kernel(const float* __restrict__ out, const float* __restrict__ bias,
                                int mask, int total, float* __restrict__ stats) {
    float s = 0.f, s2 = 0.f;
    for (int t = blockIdx.x * blockDim.x + threadIdx.x; t < total; t += gridDim.x * blockDim.x) {
        float v = out[t] + bias[t & mask];
        s += v;
        s2 += v * v;
    }
#pragma unroll
    for (int o = 16; o > 0; o >>= 1) {
        s += __shfl_xor_sync(0xffffffffu, s, o);
        s2 += __shfl_xor_sync(0xffffffffu, s2, o);
    }
    __shared__ float ss[8], ss2[8];
    int w = threadIdx.x >> 5, lane = threadIdx.x & 31;
    if (lane == 0) { ss[w] = s; ss2[w] = s2; }
    __syncthreads();
    if (threadIdx.x == 0) {
        float a = 0.f, b = 0.f;
        for (int i = 0; i < 8; i++) { a += ss[i]; b += ss2[i]; }
        atomicAdd(&stats[0], a);
        atomicAdd(&stats[1], b);
    }
}

// ---------------- apply LN + relu + optional residual ----------------
__global__ void ln_apply_kernel(const float* __restrict__ out, const float* __restrict__ bias,
                                const float* __restrict__ lg, const float* __restrict__ lb,
                                const float* __restrict__ stats, const float* __restrict__ resid,
                                float* __restrict__ hout, int mask, int total) {
    int t = blockIdx.x * blockDim.x + threadIdx.x;
    if (t >= total) return;
    float inv = 1.f / (float)total;
    float mu = stats[0] * inv;
    float var = stats[1] * inv - mu * mu;
    float rstd = rsqrtf(var + 1e-5f);
    int col = t & mask;
    float v = (out[t] + bias[col] - mu) * rstd * lg[col] + lb[col];
    v = fmaxf(v, 0.f);
    if (resid) v += resid[t];
    hout[t] = v;
}

// ---------------- global mean pool accumulation ----------------
__global__ void pool_kernel(const float* __restrict__ h, const int* __restrict__ batch,
                            float* __restrict__ Z, float* __restrict__ cnt) {
    int t = blockIdx.x * blockDim.x + threadIdx.x;
    if (t >= NN * 64) return;
    int n = t >> 6, c = t & 63;
    int g = batch[n];
    atomicAdd(&Z[g * 64 + c], h[t]);
    if (c == 0) atomicAdd(&cnt[g], 1.f);
}

// ---------------- final MLP: one block per graph ----------------
__global__ void mlp_kernel(const float* __restrict__ Z, const float* __restrict__ cnt,
                           const float* __restrict__ Wh1, const float* __restrict__ bh1,
                           const float* __restrict__ Wh2, const float* __restrict__ bh2,
                           float* __restrict__ out) {
    __shared__ float z[64];
    __shared__ float red[64];
    int g = blockIdx.x;
    int t = threadIdx.x;
    float c = fmaxf(cnt[g], 1.f);
    z[t] = Z[g * 64 + t] / c;
    __syncthreads();
    float acc = bh1[t];
#pragma unroll
    for (int k = 0; k < 64; k++) acc += z[k] * Wh1[k * 64 + t];
    acc = fmaxf(acc, 0.f);
    red[t] = acc * Wh2[t];
    __syncthreads();
    for (int s = 32; s > 0; s >>= 1) {
        if (t < s) red[t] += red[t + s];
        __syncthreads();
    }
    if (t == 0) out[g] = red[0] + bh2[0];
}

// ============================================================================
static inline void run_layer(const float* A, int din, int H,
                             const float* Wl, const float* bl,
                             const float* Wr, const float* br,
                             const float* att, const float* bias,
                             const float* lg, const float* lb,
                             const int* ei,
                             float* xl, float* xr, float* attbuf,
                             float* ex, float* den, float* stats,
                             const float* resid, float* hout) {
    int HC = H * CDIM;
    int hcShift = (HC == 256) ? 8 : 6;
    int totalNodes = NN * HC;
    int totalEdgeElems = EE * HC;

    // zero den, att-output, stats
    zero_kernel<<<(NN * H + 255) / 256, 256>>>(den, NN * H);
    zero_kernel<<<(totalNodes + 255) / 256, 256>>>(attbuf, totalNodes);
    zero_kernel<<<1, 32>>>(stats, 2);

    // fused xl/xr GEMM
    dim3 gg((NN + BM - 1) / BM, 2 * HC / BN);
    gemm_xlr_kernel<<<gg, 256>>>(A, din, NN, Wl, bl, Wr, br, xl, xr, HC);

    // edge logits + den
    {
        int warps = EE * H;
        edge_attn_kernel<<<(warps * 32 + 255) / 256, 256>>>(ei, xl, xr, att, ex, den, H, HC);
    }
    // alpha
    alpha_kernel<<<(EE * H + 255) / 256, 256>>>(ei, ex, den, H);
    // scatter
    scatter_kernel<<<(totalEdgeElems + 255) / 256, 256>>>(ei, xl, ex, attbuf, H, hcShift, totalEdgeElems);
    // layernorm stats + apply (+relu, +residual)
    ln_stats_kernel<<<2048, 256>>>(attbuf, bias, HC - 1, totalNodes, stats);
    ln_apply_kernel<<<(totalNodes + 255) / 256, 256>>>(attbuf, bias, lg, lb, stats, resid,
                                                       hout, HC - 1, totalNodes);
}

extern "C" void kernel_launch(void* const* d_in, const int* in_sizes, int n_in,
                              void* d_out, int out_size) {
    const float* x    = (const float*)d_in[0];
    const int* ei     = (const int*)d_in[1];
    const int* batch  = (const int*)d_in[2];
    // layer param blocks: 8 tensors each, starting at 3, 11, 19
    const float* Wl0 = (const float*)d_in[3];
    const float* bl0 = (const float*)d_in[4];
    const float* Wr0 = (const float*)d_in[5];
    const float* br0 = (const float*)d_in[6];
    const float* at0 = (const float*)d_in[7];
    const float* bi0 = (const float*)d_in[8];
    const float* lg0 = (const float*)d_in[9];
    const float* lb0 = (const float*)d_in[10];
    const float* Wl1 = (const float*)d_in[11];
    const float* bl1 = (const float*)d_in[12];
    const float* Wr1 = (const float*)d_in[13];
    const float* br1 = (const float*)d_in[14];
    const float* at1 = (const float*)d_in[15];
    const float* bi1 = (const float*)d_in[16];
    const float* lg1 = (const float*)d_in[17];
    const float* lb1 = (const float*)d_in[18];
    const float* Wl2 = (const float*)d_in[19];
    const float* bl2 = (const float*)d_in[20];
    const float* Wr2 = (const float*)d_in[21];
    const float* br2 = (const float*)d_in[22];
    const float* at2 = (const float*)d_in[23];
    const float* bi2 = (const float*)d_in[24];
    const float* lg2 = (const float*)d_in[25];
    const float* lb2 = (const float*)d_in[26];
    const float* Wh1 = (const float*)d_in[27];
    const float* bh1 = (const float*)d_in[28];
    const float* Wh2 = (const float*)d_in[29];
    const float* bh2 = (const float*)d_in[30];
    float* out = (float*)d_out;

    float *xl, *xr, *attb, *hA, *hB, *hC, *ex, *den, *stats, *Z, *cnt;
    cudaGetSymbolAddress((void**)&xl, g_xl);
    cudaGetSymbolAddress((void**)&xr, g_xr);
    cudaGetSymbolAddress((void**)&attb, g_att);
    cudaGetSymbolAddress((void**)&hA, g_hA);
    cudaGetSymbolAddress((void**)&hB, g_hB);
    cudaGetSymbolAddress((void**)&hC, g_hC);
    cudaGetSymbolAddress((void**)&ex, g_ex);
    cudaGetSymbolAddress((void**)&den, g_den);
    cudaGetSymbolAddress((void**)&stats, g_stats);
    cudaGetSymbolAddress((void**)&Z, g_Z);
    cudaGetSymbolAddress((void**)&cnt, g_cnt);

    // Layer 0: 128 -> 64 x 4 heads (out 256). No residual.
    run_layer(x, 128, 4, Wl0, bl0, Wr0, br0, at0, bi0, lg0, lb0, ei,
              xl, xr, attb, ex, den, stats, nullptr, hA);
    // Layer 1: 256 -> 64, 1 head. No residual.
    run_layer(hA, 256, 1, Wl1, bl1, Wr1, br1, at1, bi1, lg1, lb1, ei,
              xl, xr, attb, ex, den, stats, nullptr, hB);
    // Layer 2: 64 -> 64, 1 head. Residual (+hB).
    run_layer(hB, 64, 1, Wl2, bl2, Wr2, br2, at2, bi2, lg2, lb2, ei,
              xl, xr, attb, ex, den, stats, hB, hC);

    // global mean pool + MLP head
    zero_kernel<<<(GG * 64 + 255) / 256, 256>>>(Z, GG * 64);
    zero_kernel<<<(GG + 255) / 256, 256>>>(cnt, GG);
    pool_kernel<<<(NN * 64 + 255) / 256, 256>>>(hC, batch, Z, cnt);
    mlp_kernel<<<GG, 64>>>(Z, cnt, Wh1, bh1, Wh2, bh2, out);
}

// round 3
// speedup vs baseline: 2.1298x; 2.1298x over previous
#include <cuda_runtime.h>
#include <math.h>

#define NN 50000
#define EE 800000
#define GG 512
#define CDIM 64

// ---------------- scratch (device globals: allocation-free) ----------------
__device__ float g_xl[NN * 256];
__device__ float g_xr[NN * 256];
__device__ float g_att[NN * 256];   // attention output (bias included, pre-LN)
__device__ float g_hA[NN * 256];
__device__ float g_hB[NN * 64];
__device__ float g_hC[NN * 64];
__device__ float g_stats[2];
__device__ float g_Z[GG * 64];
__device__ float g_cnt[GG];
// CSR scratch
__device__ int g_deg[NN];
__device__ int g_ptr[NN + 1];
__device__ int g_cur[NN];
__device__ int g_csr[EE];

// ---------------- zero fills ----------------
__global__ void zero_f(float* p, int n) {
    int t = blockIdx.x * blockDim.x + threadIdx.x;
    if (t < n) p[t] = 0.f;
}
__global__ void zero_i(int* p, int n) {
    int t = blockIdx.x * blockDim.x + threadIdx.x;
    if (t < n) p[t] = 0;
}

// ---------------- CSR build ----------------
__global__ void count_kernel(const int* __restrict__ ei, int* __restrict__ deg) {
    int e = blockIdx.x * blockDim.x + threadIdx.x;
    if (e < EE) atomicAdd(&deg[ei[EE + e]], 1);
}

// single-block sequential-chunk exclusive scan (NN = 50000, 49 chunks of 1024)
__global__ void scan_kernel(const int* __restrict__ deg, int* __restrict__ ptr,
                            int* __restrict__ cur) {
    __shared__ int buf[1024];
    __shared__ int carry;
    if (threadIdx.x == 0) carry = 0;
    __syncthreads();
    for (int base = 0; base < NN; base += 1024) {
        int i = base + threadIdx.x;
        int v = (i < NN) ? deg[i] : 0;
        buf[threadIdx.x] = v;
        __syncthreads();
        for (int o = 1; o < 1024; o <<= 1) {
            int t = (threadIdx.x >= o) ? buf[threadIdx.x - o] : 0;
            __syncthreads();
            buf[threadIdx.x] += t;
            __syncthreads();
        }
        int excl = carry + buf[threadIdx.x] - v;
        if (i < NN) { ptr[i] = excl; cur[i] = excl; }
        __syncthreads();
        if (threadIdx.x == 1023) carry += buf[1023];
        __syncthreads();
    }
    if (threadIdx.x == 0) ptr[NN] = carry;
}

__global__ void fill_kernel(const int* __restrict__ ei, int* __restrict__ cur,
                            int* __restrict__ csr) {
    int e = blockIdx.x * blockDim.x + threadIdx.x;
    if (e < EE) {
        int pos = atomicAdd(&cur[ei[EE + e]], 1);
        csr[pos] = e;
    }
}

// ---------------- fused xl/xr GEMM with bias (float4 LDS) ----------------
#define BM 64
#define BN 64
#define BK 16
__global__ void gemm_xlr_kernel(const float* __restrict__ A, int din, int nrows,
                                const float* __restrict__ Wl, const float* __restrict__ bl,
                                const float* __restrict__ Wr, const float* __restrict__ br,
                                float* __restrict__ XL, float* __restrict__ XR, int HC) {
    __shared__ float As[BK][BM];
    __shared__ float Bs[BK][BN];
    int bm = blockIdx.x * BM;
    int bn = blockIdx.y * BN;
    const float* W;
    const float* bias;
    float* Out;
    int col0;
    if (bn < HC) { W = Wl; bias = bl; Out = XL; col0 = bn; }
    else         { W = Wr; bias = br; Out = XR; col0 = bn - HC; }

    int tid = threadIdx.x;
    int tx = tid & 15;
    int ty = tid >> 4;
    // A-load indices: thread handles row ar, 4-float chunk aq
    int ar = tid >> 2;
    int aq = tid & 3;
    // B-load indices
    int bkk = tid >> 4;
    int bc4 = tid & 15;
    float acc[4][4] = {};

    for (int k0 = 0; k0 < din; k0 += BK) {
        // A tile: 64 rows x 16 k, one float4 per thread
        {
            int gr = bm + ar;
            float4 v = make_float4(0.f, 0.f, 0.f, 0.f);
            if (gr < nrows) v = *(const float4*)&A[(size_t)gr * din + k0 + aq * 4];
            As[aq * 4 + 0][ar] = v.x;
            As[aq * 4 + 1][ar] = v.y;
            As[aq * 4 + 2][ar] = v.z;
            As[aq * 4 + 3][ar] = v.w;
        }
        // B tile: 16 k x 64 cols, one float4 per thread
        {
            float4 v = *(const float4*)&W[(size_t)(k0 + bkk) * HC + col0 + bc4 * 4];
            *(float4*)&Bs[bkk][bc4 * 4] = v;
        }
        __syncthreads();
#pragma unroll
        for (int kk = 0; kk < BK; kk++) {
            float4 av = *(const float4*)&As[kk][ty * 4];
            float4 bv = *(const float4*)&Bs[kk][tx * 4];
            float a[4] = {av.x, av.y, av.z, av.w};
            float b[4] = {bv.x, bv.y, bv.z, bv.w};
#pragma unroll
            for (int i = 0; i < 4; i++)
#pragma unroll
                for (int j = 0; j < 4; j++) acc[i][j] += a[i] * b[j];
        }
        __syncthreads();
    }
#pragma unroll
    for (int i = 0; i < 4; i++) {
        int r = bm + ty * 4 + i;
        if (r < nrows) {
#pragma unroll
            for (int j = 0; j < 4; j++) {
                int c = col0 + tx * 4 + j;
                Out[(size_t)r * HC + c] = acc[i][j] + bias[c];
            }
        }
    }
}

// ---------------- fused attention aggregation (CSR, no atomics) ----------------
// One warp per (dst, head). For each in-edge: logit = att . leaky_relu(xl[src]+xr[dst]),
// w = exp(logit); acc += w*xl[src]; den += w. out = acc/den + bias.
__global__ void agg_kernel(const int* __restrict__ ei, const int* __restrict__ ptr,
                           const int* __restrict__ csr,
                           const float* __restrict__ XL, const float* __restrict__ XR,
                           const float* __restrict__ att, const float* __restrict__ bias,
                           float* __restrict__ out, int H, int HC) {
    int w = (blockIdx.x * blockDim.x + threadIdx.x) >> 5;
    int lane = threadIdx.x & 31;
    if (w >= NN * H) return;
    int dst = w / H;
    int h = w - dst * H;
    const float* pr = XR + (size_t)dst * HC + h * CDIM;
    const float* pa = att + h * CDIM;
    float xr0 = pr[lane], xr1 = pr[lane + 32];
    float a0 = pa[lane], a1 = pa[lane + 32];
    float acc0 = 0.f, acc1 = 0.f, den = 0.f;
    int beg = ptr[dst], end = ptr[dst + 1];
    for (int i = beg; i < end; i++) {
        int e = csr[i];
        int src = ei[e];
        const float* pl = XL + (size_t)src * HC + h * CDIM;
        float l0 = pl[lane], l1 = pl[lane + 32];
        float s0 = l0 + xr0; s0 = (s0 > 0.f) ? s0 : 0.2f * s0;
        float s1 = l1 + xr1; s1 = (s1 > 0.f) ? s1 : 0.2f * s1;
        float d = s0 * a0 + s1 * a1;
#pragma unroll
        for (int o = 16; o > 0; o >>= 1) d += __shfl_xor_sync(0xffffffffu, d, o);
        float wgt = expf(d);
        den += wgt;
        acc0 += wgt * l0;
        acc1 += wgt * l1;
    }
    float inv = (den > 0.f) ? (1.f / den) : 0.f;
    int col = h * CDIM + lane;
    out[(size_t)dst * HC + col]      = acc0 * inv + bias[col];
    out[(size_t)dst * HC + col + 32] = acc1 * inv + bias[col + 32];
}

// ---------------- graph-layernorm stats (bias already included in buffer) --------
__global__ void ln_stats_kernel(const float* __restrict__ out, int total,
                                float* __restrict__ stats) {
    float s = 0.f, s2 = 0.f;
    for (int t = blockIdx.x * blockDim.x + threadIdx.x; t < total; t += gridDim.x * blockDim.x) {
        float v = out[t];
        s += v;
        s2 += v * v;
    }
#pragma unroll
    for (int o = 16; o > 0; o >>= 1) {
        s += __shfl_xor_sync(0xffffffffu, s, o);
        s2 += __shfl_xor_sync(0xffffffffu, s2, o);
    }
    __shared__ float ss[8], ss2[8];
    int w = threadIdx.x >> 5, lane = threadIdx.x & 31;
    if (lane == 0) { ss[w] = s; ss2[w] = s2; }
    __syncthreads();
    if (threadIdx.x == 0) {
        float a = 0.f, b = 0.f;
        for (int i = 0; i < 8; i++) { a += ss[i]; b += ss2[i]; }
        atomicAdd(&stats[0], a);
        atomicAdd(&stats[1], b);
    }
}

// ---------------- apply LN + relu + optional residual ----------------
__global__ void ln_apply_kernel(const float* __restrict__ out,
                                const float* __restrict__ lg, const float* __restrict__ lb,
                                const float* __restrict__ stats, const float* __restrict__ resid,
                                float* __restrict__ hout, int mask, int total) {
    int t = blockIdx.x * blockDim.x + threadIdx.x;
    if (t >= total) return;
    float inv = 1.f / (float)total;
    float mu = stats[0] * inv;
    float var = stats[1] * inv - mu * mu;
    float rstd = rsqrtf(var + 1e-5f);
    int col = t & mask;
    float v = (out[t] - mu) * rstd * lg[col] + lb[col];
    v = fmaxf(v, 0.f);
    if (resid) v += resid[t];
    hout[t] = v;
}

// ---------------- global mean pool ----------------
__global__ void pool_kernel(const float* __restrict__ h, const int* __restrict__ batch,
                            float* __restrict__ Z, float* __restrict__ cnt) {
    int t = blockIdx.x * blockDim.x + threadIdx.x;
    if (t >= NN * 64) return;
    int n = t >> 6, c = t & 63;
    int g = batch[n];
    atomicAdd(&Z[g * 64 + c], h[t]);
    if (c == 0) atomicAdd(&cnt[g], 1.f);
}

// ---------------- final MLP ----------------
__global__ void mlp_kernel(const float* __restrict__ Z, const float* __restrict__ cnt,
                           const float* __restrict__ Wh1, const float* __restrict__ bh1,
                           const float* __restrict__ Wh2, const float* __restrict__ bh2,
                           float* __restrict__ out) {
    __shared__ float z[64];
    __shared__ float red[64];
    int g = blockIdx.x;
    int t = threadIdx.x;
    float c = fmaxf(cnt[g], 1.f);
    z[t] = Z[g * 64 + t] / c;
    __syncthreads();
    float acc = bh1[t];
#pragma unroll
    for (int k = 0; k < 64; k++) acc += z[k] * Wh1[k * 64 + t];
    acc = fmaxf(acc, 0.f);
    red[t] = acc * Wh2[t];
    __syncthreads();
    for (int s = 32; s > 0; s >>= 1) {
        if (t < s) red[t] += red[t + s];
        __syncthreads();
    }
    if (t == 0) out[g] = red[0] + bh2[0];
}

// ============================================================================
static inline void run_layer(const float* A, int din, int H,
                             const float* Wl, const float* bl,
                             const float* Wr, const float* br,
                             const float* att, const float* bias,
                             const float* lg, const float* lb,
                             const int* ei, const int* ptr, const int* csr,
                             float* xl, float* xr, float* attbuf,
                             float* stats, const float* resid, float* hout) {
    int HC = H * CDIM;
    int totalNodes = NN * HC;

    zero_f<<<1, 32>>>(stats, 2);

    dim3 gg((NN + BM - 1) / BM, 2 * HC / BN);
    gemm_xlr_kernel<<<gg, 256>>>(A, din, NN, Wl, bl, Wr, br, xl, xr, HC);

    int warps = NN * H;
    agg_kernel<<<(warps * 32 + 255) / 256, 256>>>(ei, ptr, csr, xl, xr, att, bias,
                                                  attbuf, H, HC);

    ln_stats_kernel<<<2048, 256>>>(attbuf, totalNodes, stats);
    ln_apply_kernel<<<(totalNodes + 255) / 256, 256>>>(attbuf, lg, lb, stats, resid,
                                                       hout, HC - 1, totalNodes);
}

extern "C" void kernel_launch(void* const* d_in, const int* in_sizes, int n_in,
                              void* d_out, int out_size) {
    const float* x    = (const float*)d_in[0];
    const int* ei     = (const int*)d_in[1];
    const int* batch  = (const int*)d_in[2];
    const float* Wl0 = (const float*)d_in[3];
    const float* bl0 = (const float*)d_in[4];
    const float* Wr0 = (const float*)d_in[5];
    const float* br0 = (const float*)d_in[6];
    const float* at0 = (const float*)d_in[7];
    const float* bi0 = (const float*)d_in[8];
    const float* lg0 = (const float*)d_in[9];
    const float* lb0 = (const float*)d_in[10];
    const float* Wl1 = (const float*)d_in[11];
    const float* bl1 = (const float*)d_in[12];
    const float* Wr1 = (const float*)d_in[13];
    const float* br1 = (const float*)d_in[14];
    const float* at1 = (const float*)d_in[15];
    const float* bi1 = (const float*)d_in[16];
    const float* lg1 = (const float*)d_in[17];
    const float* lb1 = (const float*)d_in[18];
    const float* Wl2 = (const float*)d_in[19];
    const float* bl2 = (const float*)d_in[20];
    const float* Wr2 = (const float*)d_in[21];
    const float* br2 = (const float*)d_in[22];
    const float* at2 = (const float*)d_in[23];
    const float* bi2 = (const float*)d_in[24];
    const float* lg2 = (const float*)d_in[25];
    const float* lb2 = (const float*)d_in[26];
    const float* Wh1 = (const float*)d_in[27];
    const float* bh1 = (const float*)d_in[28];
    const float* Wh2 = (const float*)d_in[29];
    const float* bh2 = (const float*)d_in[30];
    float* out = (float*)d_out;

    float *xl, *xr, *attb, *hA, *hB, *hC, *stats, *Z, *cnt;
    int *deg, *ptr, *cur, *csr;
    cudaGetSymbolAddress((void**)&xl, g_xl);
    cudaGetSymbolAddress((void**)&xr, g_xr);
    cudaGetSymbolAddress((void**)&attb, g_att);
    cudaGetSymbolAddress((void**)&hA, g_hA);
    cudaGetSymbolAddress((void**)&hB, g_hB);
    cudaGetSymbolAddress((void**)&hC, g_hC);
    cudaGetSymbolAddress((void**)&stats, g_stats);
    cudaGetSymbolAddress((void**)&Z, g_Z);
    cudaGetSymbolAddress((void**)&cnt, g_cnt);
    cudaGetSymbolAddress((void**)&deg, g_deg);
    cudaGetSymbolAddress((void**)&ptr, g_ptr);
    cudaGetSymbolAddress((void**)&cur, g_cur);
    cudaGetSymbolAddress((void**)&csr, g_csr);

    // ---- build CSR (dst -> in-edges), once per launch ----
    zero_i<<<(NN + 255) / 256, 256>>>(deg, NN);
    count_kernel<<<(EE + 255) / 256, 256>>>(ei, deg);
    scan_kernel<<<1, 1024>>>(deg, ptr, cur);
    fill_kernel<<<(EE + 255) / 256, 256>>>(ei, cur, csr);

    // Layer 0: 128 -> 64 x 4 heads (out 256). No residual.
    run_layer(x, 128, 4, Wl0, bl0, Wr0, br0, at0, bi0, lg0, lb0, ei, ptr, csr,
              xl, xr, attb, stats, nullptr, hA);
    // Layer 1: 256 -> 64, 1 head. No residual.
    run_layer(hA, 256, 1, Wl1, bl1, Wr1, br1, at1, bi1, lg1, lb1, ei, ptr, csr,
              xl, xr, attb, stats, nullptr, hB);
    // Layer 2: 64 -> 64, 1 head. Residual (+hB).
    run_layer(hB, 64, 1, Wl2, bl2, Wr2, br2, at2, bi2, lg2, lb2, ei, ptr, csr,
              xl, xr, attb, stats, hB, hC);

    // global mean pool + MLP head
    zero_f<<<(GG * 64 + 255) / 256, 256>>>(Z, GG * 64);
    zero_f<<<(GG + 255) / 256, 256>>>(cnt, GG);
    pool_kernel<<<(NN * 64 + 255) / 256, 256>>>(hC, batch, Z, cnt);
    mlp_kernel<<<GG, 64>>>(Z, cnt, Wh1, bh1, Wh2, bh2, out);
}

// round 4
// speedup vs baseline: 2.9938x; 1.4057x over previous
#include <cuda_runtime.h>
#include <math.h>

#define NN 50000
#define EE 800000
#define GG 512
#define CDIM 64

// ---------------- scratch (device globals: allocation-free) ----------------
__device__ float g_xl[NN * 256];
__device__ float g_xr[NN * 256];
__device__ float g_att[NN * 256];   // attention output (bias included, pre-LN)
__device__ float g_hA[NN * 256];
__device__ float g_hB[NN * 64];
__device__ float g_hC[NN * 64];
__device__ float g_stats[2];
// CSR scratch
__device__ int g_deg[NN];
__device__ int g_ptr[NN + 1];
__device__ int g_cur[NN];
__device__ int g_csr[EE];

// ---------------- zero fills ----------------
__global__ void zero_f(float* p, int n) {
    int t = blockIdx.x * blockDim.x + threadIdx.x;
    if (t < n) p[t] = 0.f;
}
__global__ void zero_i(int* p, int n) {
    int t = blockIdx.x * blockDim.x + threadIdx.x;
    if (t < n) p[t] = 0;
}

// ---------------- CSR build ----------------
__global__ void count_kernel(const int* __restrict__ ei, int* __restrict__ deg) {
    int e = blockIdx.x * blockDim.x + threadIdx.x;
    if (e < EE) atomicAdd(&deg[ei[EE + e]], 1);
}

// single-block shuffle-based exclusive scan over NN elems (chunks of 1024)
__global__ void scan_kernel(const int* __restrict__ deg, int* __restrict__ ptr,
                            int* __restrict__ cur) {
    __shared__ int wsum[32];
    __shared__ int s_carry;
    int lane = threadIdx.x & 31;
    int wid = threadIdx.x >> 5;
    if (threadIdx.x == 0) s_carry = 0;
    __syncthreads();
    for (int base = 0; base < NN; base += 1024) {
        int i = base + threadIdx.x;
        int v = (i < NN) ? deg[i] : 0;
        // warp inclusive scan
        int x = v;
#pragma unroll
        for (int o = 1; o < 32; o <<= 1) {
            int y = __shfl_up_sync(0xffffffffu, x, o);
            if (lane >= o) x += y;
        }
        if (lane == 31) wsum[wid] = x;
        __syncthreads();
        if (wid == 0) {
            int w = wsum[lane];
#pragma unroll
            for (int o = 1; o < 32; o <<= 1) {
                int y = __shfl_up_sync(0xffffffffu, w, o);
                if (lane >= o) w += y;
            }
            wsum[lane] = w;
        }
        __syncthreads();
        int wpre = (wid > 0) ? wsum[wid - 1] : 0;
        int excl = s_carry + wpre + x - v;
        if (i < NN) { ptr[i] = excl; cur[i] = excl; }
        __syncthreads();
        if (threadIdx.x == 1023) s_carry += wpre + x;  // total of chunk
        __syncthreads();
    }
    if (threadIdx.x == 0) ptr[NN] = s_carry;
}

__global__ void fill_kernel(const int* __restrict__ ei, int* __restrict__ cur,
                            int* __restrict__ csr) {
    int e = blockIdx.x * blockDim.x + threadIdx.x;
    if (e < EE) {
        int pos = atomicAdd(&cur[ei[EE + e]], 1);
        csr[pos] = e;
    }
}

// ---------------- fused xl/xr GEMM with bias: 128x64 tile, 8x4 micro ----------------
#define GBM 128
#define GBN 64
#define GBK 16
__global__ void gemm_xlr_kernel(const float* __restrict__ A, int din, int nrows,
                                const float* __restrict__ Wl, const float* __restrict__ bl,
                                const float* __restrict__ Wr, const float* __restrict__ br,
                                float* __restrict__ XL, float* __restrict__ XR, int HC) {
    __shared__ float As[GBK][GBM];
    __shared__ float Bs[GBK][GBN];
    int bm = blockIdx.x * GBM;
    int bn = blockIdx.y * GBN;
    const float* W;
    const float* bias;
    float* Out;
    int col0;
    if (bn < HC) { W = Wl; bias = bl; Out = XL; col0 = bn; }
    else         { W = Wr; bias = br; Out = XR; col0 = bn - HC; }

    int tid = threadIdx.x;
    int tx = tid & 15;   // 16 col-groups of 4
    int ty = tid >> 4;   // 16 row-groups of 8
    int bkk = tid >> 4;  // B load: k row
    int bc4 = tid & 15;  // B load: col chunk
    float acc[8][4] = {};

    for (int k0 = 0; k0 < din; k0 += GBK) {
        // A tile: 128 rows x 16 k. 512 float4s, 2 per thread.
#pragma unroll
        for (int i = 0; i < 2; i++) {
            int f = tid + i * 256;
            int r = f >> 2;
            int kq = f & 3;
            int gr = bm + r;
            float4 v = make_float4(0.f, 0.f, 0.f, 0.f);
            if (gr < nrows) v = *(const float4*)&A[(size_t)gr * din + k0 + kq * 4];
            As[kq * 4 + 0][r] = v.x;
            As[kq * 4 + 1][r] = v.y;
            As[kq * 4 + 2][r] = v.z;
            As[kq * 4 + 3][r] = v.w;
        }
        // B tile: 16 k x 64 cols. 1 float4 per thread.
        *(float4*)&Bs[bkk][bc4 * 4] =
            *(const float4*)&W[(size_t)(k0 + bkk) * HC + col0 + bc4 * 4];
        __syncthreads();
#pragma unroll
        for (int kk = 0; kk < GBK; kk++) {
            float4 av0 = *(const float4*)&As[kk][ty * 8];
            float4 av1 = *(const float4*)&As[kk][ty * 8 + 4];
            float4 bv = *(const float4*)&Bs[kk][tx * 4];
            float a[8] = {av0.x, av0.y, av0.z, av0.w, av1.x, av1.y, av1.z, av1.w};
            float b[4] = {bv.x, bv.y, bv.z, bv.w};
#pragma unroll
            for (int i = 0; i < 8; i++)
#pragma unroll
                for (int j = 0; j < 4; j++) acc[i][j] += a[i] * b[j];
        }
        __syncthreads();
    }
#pragma unroll
    for (int i = 0; i < 8; i++) {
        int r = bm + ty * 8 + i;
        if (r < nrows) {
            float4 o;
            int c = col0 + tx * 4;
            o.x = acc[i][0] + bias[c + 0];
            o.y = acc[i][1] + bias[c + 1];
            o.z = acc[i][2] + bias[c + 2];
            o.w = acc[i][3] + bias[c + 3];
            *(float4*)&Out[(size_t)r * HC + c] = o;
        }
    }
}

// ---------------- fused attention aggregation (CSR, no atomics, 2x unroll) -------
__global__ void agg_kernel(const int* __restrict__ ei, const int* __restrict__ ptr,
                           const int* __restrict__ csr,
                           const float* __restrict__ XL, const float* __restrict__ XR,
                           const float* __restrict__ att, const float* __restrict__ bias,
                           float* __restrict__ out, int H, int HC) {
    int w = (blockIdx.x * blockDim.x + threadIdx.x) >> 5;
    int lane = threadIdx.x & 31;
    if (w >= NN * H) return;
    int dst = w / H;
    int h = w - dst * H;
    const float* pr = XR + (size_t)dst * HC + h * CDIM;
    const float* pa = att + h * CDIM;
    float xr0 = pr[lane], xr1 = pr[lane + 32];
    float a0 = pa[lane], a1 = pa[lane + 32];
    float acc0 = 0.f, acc1 = 0.f, den = 0.f;
    int beg = ptr[dst], end = ptr[dst + 1];
    int i = beg;
    for (; i + 2 <= end; i += 2) {
        int e0 = csr[i], e1 = csr[i + 1];
        int s0 = ei[e0], s1 = ei[e1];
        const float* p0 = XL + (size_t)s0 * HC + h * CDIM;
        const float* p1 = XL + (size_t)s1 * HC + h * CDIM;
        float l00 = p0[lane], l01 = p0[lane + 32];
        float l10 = p1[lane], l11 = p1[lane + 32];
        float t00 = l00 + xr0; t00 = (t00 > 0.f) ? t00 : 0.2f * t00;
        float t01 = l01 + xr1; t01 = (t01 > 0.f) ? t01 : 0.2f * t01;
        float t10 = l10 + xr0; t10 = (t10 > 0.f) ? t10 : 0.2f * t10;
        float t11 = l11 + xr1; t11 = (t11 > 0.f) ? t11 : 0.2f * t11;
        float d0 = t00 * a0 + t01 * a1;
        float d1 = t10 * a0 + t11 * a1;
#pragma unroll
        for (int o = 16; o > 0; o >>= 1) {
            d0 += __shfl_xor_sync(0xffffffffu, d0, o);
            d1 += __shfl_xor_sync(0xffffffffu, d1, o);
        }
        float w0 = expf(d0), w1 = expf(d1);
        den += w0 + w1;
        acc0 += w0 * l00 + w1 * l10;
        acc1 += w0 * l01 + w1 * l11;
    }
    if (i < end) {
        int e = csr[i];
        int src = ei[e];
        const float* pl = XL + (size_t)src * HC + h * CDIM;
        float l0 = pl[lane], l1 = pl[lane + 32];
        float s0 = l0 + xr0; s0 = (s0 > 0.f) ? s0 : 0.2f * s0;
        float s1 = l1 + xr1; s1 = (s1 > 0.f) ? s1 : 0.2f * s1;
        float d = s0 * a0 + s1 * a1;
#pragma unroll
        for (int o = 16; o > 0; o >>= 1) d += __shfl_xor_sync(0xffffffffu, d, o);
        float wgt = expf(d);
        den += wgt;
        acc0 += wgt * l0;
        acc1 += wgt * l1;
    }
    float inv = (den > 0.f) ? (1.f / den) : 0.f;
    int col = h * CDIM + lane;
    out[(size_t)dst * HC + col]      = acc0 * inv + bias[col];
    out[(size_t)dst * HC + col + 32] = acc1 * inv + bias[col + 32];
}

// ---------------- graph-layernorm stats (float4, bias already in buffer) --------
__global__ void ln_stats_kernel(const float* __restrict__ out, int total4,
                                float* __restrict__ stats) {
    float s = 0.f, s2 = 0.f;
    const float4* p = (const float4*)out;
    for (int t = blockIdx.x * blockDim.x + threadIdx.x; t < total4; t += gridDim.x * blockDim.x) {
        float4 v = p[t];
        s += v.x + v.y + v.z + v.w;
        s2 += v.x * v.x + v.y * v.y + v.z * v.z + v.w * v.w;
    }
#pragma unroll
    for (int o = 16; o > 0; o >>= 1) {
        s += __shfl_xor_sync(0xffffffffu, s, o);
        s2 += __shfl_xor_sync(0xffffffffu, s2, o);
    }
    __shared__ float ss[8], ss2[8];
    int w = threadIdx.x >> 5, lane = threadIdx.x & 31;
    if (lane == 0) { ss[w] = s; ss2[w] = s2; }
    __syncthreads();
    if (threadIdx.x == 0) {
        float a = 0.f, b = 0.f;
        for (int i = 0; i < 8; i++) { a += ss[i]; b += ss2[i]; }
        atomicAdd(&stats[0], a);
        atomicAdd(&stats[1], b);
    }
}

// ---------------- apply LN + relu + optional residual (float4) ----------------
__global__ void ln_apply_kernel(const float* __restrict__ out,
                                const float* __restrict__ lg, const float* __restrict__ lb,
                                const float* __restrict__ stats, const float* __restrict__ resid,
                                float* __restrict__ hout, int mask, int total) {
    int t4 = (blockIdx.x * blockDim.x + threadIdx.x) * 4;
    if (t4 >= total) return;
    float inv = 1.f / (float)total;
    float mu = stats[0] * inv;
    float var = stats[1] * inv - mu * mu;
    float rstd = rsqrtf(var + 1e-5f);
    int col = t4 & mask;
    float4 v = *(const float4*)&out[t4];
    float4 r;
    r.x = fmaxf((v.x - mu) * rstd * lg[col + 0] + lb[col + 0], 0.f);
    r.y = fmaxf((v.y - mu) * rstd * lg[col + 1] + lb[col + 1], 0.f);
    r.z = fmaxf((v.z - mu) * rstd * lg[col + 2] + lb[col + 2], 0.f);
    r.w = fmaxf((v.w - mu) * rstd * lg[col + 3] + lb[col + 3], 0.f);
    if (resid) {
        float4 q = *(const float4*)&resid[t4];
        r.x += q.x; r.y += q.y; r.z += q.z; r.w += q.w;
    }
    *(float4*)&hout[t4] = r;
}

// ---------------- fused pool + MLP: one block per graph (batch is sorted) -------
__global__ void pool_mlp_kernel(const float* __restrict__ h, const int* __restrict__ batch,
                                const float* __restrict__ Wh1, const float* __restrict__ bh1,
                                const float* __restrict__ Wh2, const float* __restrict__ bh2,
                                float* __restrict__ out) {
    __shared__ float red[256];
    __shared__ float z[64];
    int g = blockIdx.x;
    int t = threadIdx.x;
    // binary search [lo, hi) of nodes with batch == g
    int lo = 0, hi_b = NN;
    while (lo < hi_b) { int m = (lo + hi_b) >> 1; if (batch[m] < g) lo = m + 1; else hi_b = m; }
    int lo2 = lo, hi2 = NN;
    while (lo2 < hi2) { int m = (lo2 + hi2) >> 1; if (batch[m] < g + 1) lo2 = m + 1; else hi2 = m; }
    int beg = lo, end = lo2;
    int c = t & 63;
    int rg = t >> 6;  // 4 row groups
    float acc = 0.f;
    for (int n = beg + rg; n < end; n += 4) acc += h[(size_t)n * 64 + c];
    red[t] = acc;
    __syncthreads();
    if (t < 64) {
        float s = red[t] + red[t + 64] + red[t + 128] + red[t + 192];
        float cnt = fmaxf((float)(end - beg), 1.f);
        z[t] = s / cnt;
    }
    __syncthreads();
    if (t < 64) {
        float a = bh1[t];
#pragma unroll
        for (int k = 0; k < 64; k++) a += z[k] * Wh1[k * 64 + t];
        a = fmaxf(a, 0.f);
        red[t] = a * Wh2[t];
    }
    __syncthreads();
    if (t < 32) {
        float v = red[t] + red[t + 32];
#pragma unroll
        for (int o = 16; o > 0; o >>= 1) v += __shfl_xor_sync(0xffffffffu, v, o);
        if (t == 0) out[g] = v + bh2[0];
    }
}

// ============================================================================
static inline void run_layer(const float* A, int din, int H,
                             const float* Wl, const float* bl,
                             const float* Wr, const float* br,
                             const float* att, const float* bias,
                             const float* lg, const float* lb,
                             const int* ei, const int* ptr, const int* csr,
                             float* xl, float* xr, float* attbuf,
                             float* stats, const float* resid, float* hout) {
    int HC = H * CDIM;
    int totalNodes = NN * HC;

    zero_f<<<1, 32>>>(stats, 2);

    dim3 gg((NN + GBM - 1) / GBM, 2 * HC / GBN);
    gemm_xlr_kernel<<<gg, 256>>>(A, din, NN, Wl, bl, Wr, br, xl, xr, HC);

    int warps = NN * H;
    agg_kernel<<<(warps * 32 + 255) / 256, 256>>>(ei, ptr, csr, xl, xr, att, bias,
                                                  attbuf, H, HC);

    ln_stats_kernel<<<1024, 256>>>(attbuf, totalNodes / 4, stats);
    ln_apply_kernel<<<(totalNodes / 4 + 255) / 256, 256>>>(attbuf, lg, lb, stats, resid,
                                                           hout, HC - 1, totalNodes);
}

extern "C" void kernel_launch(void* const* d_in, const int* in_sizes, int n_in,
                              void* d_out, int out_size) {
    const float* x    = (const float*)d_in[0];
    const int* ei     = (const int*)d_in[1];
    const int* batch  = (const int*)d_in[2];
    const float* Wl0 = (const float*)d_in[3];
    const float* bl0 = (const float*)d_in[4];
    const float* Wr0 = (const float*)d_in[5];
    const float* br0 = (const float*)d_in[6];
    const float* at0 = (const float*)d_in[7];
    const float* bi0 = (const float*)d_in[8];
    const float* lg0 = (const float*)d_in[9];
    const float* lb0 = (const float*)d_in[10];
    const float* Wl1 = (const float*)d_in[11];
    const float* bl1 = (const float*)d_in[12];
    const float* Wr1 = (const float*)d_in[13];
    const float* br1 = (const float*)d_in[14];
    const float* at1 = (const float*)d_in[15];
    const float* bi1 = (const float*)d_in[16];
    const float* lg1 = (const float*)d_in[17];
    const float* lb1 = (const float*)d_in[18];
    const float* Wl2 = (const float*)d_in[19];
    const float* bl2 = (const float*)d_in[20];
    const float* Wr2 = (const float*)d_in[21];
    const float* br2 = (const float*)d_in[22];
    const float* at2 = (const float*)d_in[23];
    const float* bi2 = (const float*)d_in[24];
    const float* lg2 = (const float*)d_in[25];
    const float* lb2 = (const float*)d_in[26];
    const float* Wh1 = (const float*)d_in[27];
    const float* bh1 = (const float*)d_in[28];
    const float* Wh2 = (const float*)d_in[29];
    const float* bh2 = (const float*)d_in[30];
    float* out = (float*)d_out;

    float *xl, *xr, *attb, *hA, *hB, *hC, *stats;
    int *deg, *ptr, *cur, *csr;
    cudaGetSymbolAddress((void**)&xl, g_xl);
    cudaGetSymbolAddress((void**)&xr, g_xr);
    cudaGetSymbolAddress((void**)&attb, g_att);
    cudaGetSymbolAddress((void**)&hA, g_hA);
    cudaGetSymbolAddress((void**)&hB, g_hB);
    cudaGetSymbolAddress((void**)&hC, g_hC);
    cudaGetSymbolAddress((void**)&stats, g_stats);
    cudaGetSymbolAddress((void**)&deg, g_deg);
    cudaGetSymbolAddress((void**)&ptr, g_ptr);
    cudaGetSymbolAddress((void**)&cur, g_cur);
    cudaGetSymbolAddress((void**)&csr, g_csr);

    // ---- build CSR (dst -> in-edges) ----
    zero_i<<<(NN + 255) / 256, 256>>>(deg, NN);
    count_kernel<<<(EE + 255) / 256, 256>>>(ei, deg);
    scan_kernel<<<1, 1024>>>(deg, ptr, cur);
    fill_kernel<<<(EE + 255) / 256, 256>>>(ei, cur, csr);

    // Layer 0: 128 -> 64 x 4 heads (out 256). No residual.
    run_layer(x, 128, 4, Wl0, bl0, Wr0, br0, at0, bi0, lg0, lb0, ei, ptr, csr,
              xl, xr, attb, stats, nullptr, hA);
    // Layer 1: 256 -> 64, 1 head. No residual.
    run_layer(hA, 256, 1, Wl1, bl1, Wr1, br1, at1, bi1, lg1, lb1, ei, ptr, csr,
              xl, xr, attb, stats, nullptr, hB);
    // Layer 2: 64 -> 64, 1 head. Residual (+hB).
    run_layer(hB, 64, 1, Wl2, bl2, Wr2, br2, at2, bi2, lg2, lb2, ei, ptr, csr,
              xl, xr, attb, stats, hB, hC);

    // fused global mean pool + MLP head
    pool_mlp_kernel<<<GG, 256>>>(hC, batch, Wh1, bh1, Wh2, bh2, out);
}